// round 2
// baseline (speedup 1.0000x reference)
#include <cuda_runtime.h>

#define B_ROWS 8192
#define P_ROWS 1024
#define D_DIM  256
#define NPART  128   // partial-reduction blocks for prototypes

// Scratch (allocation-free rule: device globals)
__device__ float g_partial[NPART * D_DIM];  // per-block column sums of prototypes
__device__ float g_partial2[NPART];         // per-block sum of squares
__device__ float g_m2[D_DIM];               // 2 * mean_p(proto[:,d])
__device__ float g_c;                       // mean_p ||proto_p||^2

// ---------------------------------------------------------------------------
// K1: partial reduction over prototypes. Block i handles rows [i*8, i*8+8).
// Thread d accumulates column d. Coalesced: consecutive threads -> consecutive d.
// ---------------------------------------------------------------------------
__global__ void k1_proto_partial(const float* __restrict__ proto) {
    const int d = threadIdx.x;            // 0..255
    const int blk = blockIdx.x;           // 0..127
    const int row0 = blk * (P_ROWS / NPART);

    float s = 0.0f, sq = 0.0f;
#pragma unroll
    for (int r = 0; r < P_ROWS / NPART; ++r) {
        float v = proto[(row0 + r) * D_DIM + d];
        s += v;
        sq += v * v;
    }
    g_partial[blk * D_DIM + d] = s;

    // block-reduce sq over 256 threads
    __shared__ float sm[D_DIM];
    sm[d] = sq;
    __syncthreads();
    for (int off = D_DIM / 2; off >= 32; off >>= 1) {
        if (d < off) sm[d] += sm[d + off];
        __syncthreads();
    }
    if (d < 32) {
        float v = sm[d];
#pragma unroll
        for (int o = 16; o > 0; o >>= 1)
            v += __shfl_down_sync(0xFFFFFFFFu, v, o);
        if (d == 0) g_partial2[blk] = v;
    }
}

// ---------------------------------------------------------------------------
// K2: combine partials (single block, deterministic).
// ---------------------------------------------------------------------------
__global__ void k2_combine() {
    const int d = threadIdx.x;  // 0..255
    float s = 0.0f;
#pragma unroll 8
    for (int i = 0; i < NPART; ++i)
        s += g_partial[i * D_DIM + d];
    g_m2[d] = 2.0f * s * (1.0f / (float)P_ROWS);

    // reduce the 128 square-partials with the first 128 threads
    __shared__ float sm[NPART];
    if (d < NPART) sm[d] = g_partial2[d];
    __syncthreads();
    if (d < 64) sm[d] += sm[d + 64];
    __syncthreads();
    if (d < 32) {
        float v = sm[d] + sm[d + 32];
#pragma unroll
        for (int o = 16; o > 0; o >>= 1)
            v += __shfl_down_sync(0xFFFFFFFFu, v, o);
        if (d == 0) g_c = v * (1.0f / (float)P_ROWS);
    }
}

// ---------------------------------------------------------------------------
// K3: main streaming pass. One warp per input row; 8 warps (256 thr) per block.
// Lane L covers d in [8L, 8L+8): two float4 loads -> warp covers 1024B
// contiguously. out[b] = sum_d x*(x - 2*mean) + c.
// ---------------------------------------------------------------------------
__global__ void __launch_bounds__(256) k3_main(const float* __restrict__ x,
                                              float* __restrict__ out) {
    const int lane = threadIdx.x & 31;
    const int warp = threadIdx.x >> 5;
    const int row = blockIdx.x * 8 + warp;   // gridDim = 1024 -> rows 0..8191

    const int d0 = lane * 8;
    const float4* xr = reinterpret_cast<const float4*>(x + row * D_DIM + d0);
    const float4* mr = reinterpret_cast<const float4*>(g_m2 + d0);

    float4 x0 = xr[0];
    float4 x1 = xr[1];
    float4 m0 = mr[0];
    float4 m1 = mr[1];

    float acc;
    acc  = x0.x * (x0.x - m0.x);
    acc += x0.y * (x0.y - m0.y);
    acc += x0.z * (x0.z - m0.z);
    acc += x0.w * (x0.w - m0.w);
    acc += x1.x * (x1.x - m1.x);
    acc += x1.y * (x1.y - m1.y);
    acc += x1.z * (x1.z - m1.z);
    acc += x1.w * (x1.w - m1.w);

#pragma unroll
    for (int o = 16; o > 0; o >>= 1)
        acc += __shfl_down_sync(0xFFFFFFFFu, acc, o);

    if (lane == 0) out[row] = acc + g_c;
}

extern "C" void kernel_launch(void* const* d_in, const int* in_sizes, int n_in,
                              void* d_out, int out_size) {
    const float* x     = (const float*)d_in[0];  // (8192, 256) float32
    const float* proto = (const float*)d_in[1];  // (1024, 256) float32
    float* out = (float*)d_out;                  // (8192,) float32

    k1_proto_partial<<<NPART, D_DIM>>>(proto);
    k2_combine<<<1, D_DIM>>>();
    k3_main<<<B_ROWS / 8, 256>>>(x, out);
}

// round 3
// speedup vs baseline: 1.4060x; 1.4060x over previous
#include <cuda_runtime.h>

#define B_ROWS 8192
#define P_ROWS 1024
#define D_DIM  256
#define NPART  64          // prototype partial-reduction blocks
#define GRID   592         // 148 SMs * 4 blocks -> fully resident (256 thr, ~32 regs)
#define NWARP  8

// Scratch + barrier state (allocation-free rule: device globals, zero-init at load)
__device__ float g_partial[NPART * D_DIM];   // per-block column sums of prototypes
__device__ float g_p2[NPART];                // per-block sum of squares
__device__ unsigned int g_count = 0;         // phase-1 arrival counter
__device__ unsigned int g_done  = 0;         // completion counter (for reset)

__global__ void __launch_bounds__(256, 4)
som_fused(const float* __restrict__ x,
          const float* __restrict__ proto,
          float* __restrict__ out) {
    const int tid  = threadIdx.x;
    const int lane = tid & 31;
    const int warp = tid >> 5;
    const int blk  = blockIdx.x;

    __shared__ __align__(16) float sm_grp[4 * D_DIM];  // 4 row-group partials
    __shared__ __align__(16) float sm_m2[D_DIM];       // 2 * mean_p proto[:,d]
    __shared__ float sm_p2g[NWARP];
    __shared__ float sm_c;

    // ---------------- Phase 1: prototype partials (blocks 0..NPART-1) ----------
    if (blk < NPART) {
        // 16 rows per block. Thread layout: c4 = tid%64 -> columns [4c4,4c4+4),
        // g = tid/64 -> 4 rows each. All loads are float4, fully coalesced.
        const int c4   = tid & 63;
        const int g    = tid >> 6;
        const int row0 = blk * (P_ROWS / NPART) + g * 4;

        float4 s = make_float4(0.f, 0.f, 0.f, 0.f);
        float sq = 0.f;
#pragma unroll
        for (int r = 0; r < 4; ++r) {
            float4 v = *reinterpret_cast<const float4*>(
                proto + (row0 + r) * D_DIM + c4 * 4);
            s.x += v.x; s.y += v.y; s.z += v.z; s.w += v.w;
            sq  += v.x * v.x + v.y * v.y + v.z * v.z + v.w * v.w;
        }
        *reinterpret_cast<float4*>(&sm_grp[g * D_DIM + c4 * 4]) = s;

#pragma unroll
        for (int o = 16; o > 0; o >>= 1)
            sq += __shfl_down_sync(0xFFFFFFFFu, sq, o);
        if (lane == 0) sm_p2g[warp] = sq;
        __syncthreads();

        // thread d combines the 4 row-groups for column d
        float col = sm_grp[tid] + sm_grp[D_DIM + tid] +
                    sm_grp[2 * D_DIM + tid] + sm_grp[3 * D_DIM + tid];
        g_partial[blk * D_DIM + tid] = col;
        if (tid == 0) {
            float p2 = 0.f;
#pragma unroll
            for (int i = 0; i < NWARP; ++i) p2 += sm_p2g[i];
            g_p2[blk] = p2;
        }
        __syncthreads();                 // all global writes of this block issued
        if (tid == 0) {
            __threadfence();             // make partials visible before arrival
            atomicAdd(&g_count, 1u);
        }
    }

    // ---------------- Grid barrier: wait for all NPART partials ----------------
    if (tid == 0) {
        while (atomicAdd(&g_count, 0u) < NPART) { }
    }
    __syncthreads();
    __threadfence();                     // order partial reads after observation

    // ---------------- Combine (every block, redundant, L2-resident 66KB) -------
    {
        const int c4 = tid & 63;
        const int g  = tid >> 6;
        float4 s = make_float4(0.f, 0.f, 0.f, 0.f);
#pragma unroll
        for (int i = 0; i < NPART / 4; ++i) {       // 16 partial rows per group
            float4 v = *reinterpret_cast<const float4*>(
                &g_partial[(g * (NPART / 4) + i) * D_DIM + c4 * 4]);
            s.x += v.x; s.y += v.y; s.z += v.z; s.w += v.w;
        }
        *reinterpret_cast<float4*>(&sm_grp[g * D_DIM + c4 * 4]) = s;

        if (warp == 0) {                 // reduce the 64 square-partials
            float v = g_p2[lane] + g_p2[lane + 32];
#pragma unroll
            for (int o = 16; o > 0; o >>= 1)
                v += __shfl_down_sync(0xFFFFFFFFu, v, o);
            if (lane == 0) sm_c = v * (1.0f / (float)P_ROWS);
        }
        __syncthreads();

        float m = sm_grp[tid] + sm_grp[D_DIM + tid] +
                  sm_grp[2 * D_DIM + tid] + sm_grp[3 * D_DIM + tid];
        sm_m2[tid] = m * (2.0f / (float)P_ROWS);
        __syncthreads();
    }

    // ---------------- Phase 3: stream inputs, warp per row ---------------------
    const float c  = sm_c;
    const int  d0  = lane * 8;
    const float4 m0 = *reinterpret_cast<const float4*>(&sm_m2[d0]);
    const float4 m1 = *reinterpret_cast<const float4*>(&sm_m2[d0 + 4]);
    const int gw = blk * NWARP + warp;   // global warp id, 0..4735

    for (int row = gw; row < B_ROWS; row += GRID * NWARP) {
        const float4* xr = reinterpret_cast<const float4*>(x + row * D_DIM + d0);
        float4 x0 = xr[0];
        float4 x1 = xr[1];

        float acc;
        acc  = x0.x * (x0.x - m0.x);
        acc += x0.y * (x0.y - m0.y);
        acc += x0.z * (x0.z - m0.z);
        acc += x0.w * (x0.w - m0.w);
        acc += x1.x * (x1.x - m1.x);
        acc += x1.y * (x1.y - m1.y);
        acc += x1.z * (x1.z - m1.z);
        acc += x1.w * (x1.w - m1.w);

#pragma unroll
        for (int o = 16; o > 0; o >>= 1)
            acc += __shfl_down_sync(0xFFFFFFFFu, acc, o);

        if (lane == 0) out[row] = acc + c;
    }

    // ---------------- Reset barrier state for the next graph replay ------------
    __syncthreads();
    if (tid == 0) {
        unsigned int d = atomicAdd(&g_done, 1u);
        if (d == GRID - 1) {             // last block out resets everything
            g_count = 0;
            g_done  = 0;
            __threadfence();
        }
    }
}

extern "C" void kernel_launch(void* const* d_in, const int* in_sizes, int n_in,
                              void* d_out, int out_size) {
    const float* x     = (const float*)d_in[0];  // (8192, 256) float32
    const float* proto = (const float*)d_in[1];  // (1024, 256) float32
    float* out = (float*)d_out;                  // (8192,) float32

    som_fused<<<GRID, 256>>>(x, proto, out);
}